// round 10
// baseline (speedup 1.0000x reference)
#include <cuda_runtime.h>
#include <cuda_fp16.h>
#include <cstdint>
#include <math.h>

#define N_NODES 50000
#define N_EDGES 200000
#define IN_CH   256
#define HID     768
#define N_REL   5
#define N_BASES 4
#define K1      (5*IN_CH)   /* 1280: [x | Z0..Z3] layer 1 */
#define K2      (5*HID)     /* 3840: [h | Z0..Z3] layer 2 */

// ---------------- static device scratch (no allocations allowed) -------------
__device__ __half g_A1[(size_t)N_NODES * K1];   // layer-1 GEMM A operand (122 MB)
__device__ __half g_A2[(size_t)N_NODES * K2];   // layer-2 GEMM A operand (366 MB)
__device__ __half g_Wh1[(size_t)HID * K1];      // layer-1 B^T (K-major, half)
__device__ __half g_Wh2[(size_t)HID * K2];      // layer-2 B^T (K-major, half)
__device__ float  g_P[(size_t)N_NODES * HID];   // partial GEMM accumulator (153 MB)
__device__ int    g_cnt[N_NODES * N_REL];
__device__ int    g_deg[N_NODES];
__device__ int    g_off[N_NODES];
__device__ int    g_pos[N_NODES];
__device__ int2   g_es[N_EDGES];                // per-slot {src|(t<<20), bits(1/cnt)}
__device__ int    g_esrc[N_EDGES];
__device__ int    g_edst[N_EDGES];
__device__ int    g_etyp[N_EDGES];
__device__ int    g_total;
__device__ int    g_is64;

// ============================ helpers ====================================
__device__ __forceinline__ void cp16(uint32_t dst, const void* src, int sz) {
    asm volatile("cp.async.cg.shared.global [%0], [%1], 16, %2;"
                 :: "r"(dst), "l"(src), "r"(sz));
}
__device__ __forceinline__ uint32_t smem_u32(const void* p) {
    uint32_t a;
    asm("{ .reg .u64 t; cvta.to.shared.u64 t, %1; cvt.u32.u64 %0, t; }"
        : "=r"(a) : "l"(p));
    return a;
}
__device__ __forceinline__ void mma16n8k16(float* d, const uint32_t* a, const uint32_t* b) {
    asm volatile(
        "mma.sync.aligned.m16n8k16.row.col.f32.f16.f16.f32 "
        "{%0,%1,%2,%3}, {%4,%5,%6,%7}, {%8,%9}, {%0,%1,%2,%3};"
        : "+f"(d[0]), "+f"(d[1]), "+f"(d[2]), "+f"(d[3])
        : "r"(a[0]), "r"(a[1]), "r"(a[2]), "r"(a[3]), "r"(b[0]), "r"(b[1]));
}
__device__ __forceinline__ void ldsm4(uint32_t& r0, uint32_t& r1, uint32_t& r2,
                                      uint32_t& r3, uint32_t addr) {
    asm volatile("ldmatrix.sync.aligned.m8n8.x4.shared.b16 {%0,%1,%2,%3}, [%4];"
                 : "=r"(r0), "=r"(r1), "=r"(r2), "=r"(r3) : "r"(addr));
}

// ====================== fp16 mma.sync GEMM (fp32 accum) ======================
// acc = A[M, K] @ W^T  (A row stride lda, W row stride ldw; both K-major half)
// epi=0: dst float = acc                         (partial -> g_P)
// epi=1: acc += P, + bias, BN+ReLU -> half out_h (stride K2; layer-1 final)
// epi=2: acc += P, + bias -> float dst           (layer-2 final)
#define BM 128
#define BN 256
#define BK 32
#define AST 40                              /* padded row stride in halves */
#define SA_BUF (BM * AST)
#define SB_BUF (BN * AST)
#define STAGES 3
#define SM_TOTAL (STAGES * (SA_BUF + SB_BUF) * 2)   /* 92160 bytes */

__global__ void __launch_bounds__(256, 1)
k_gemm_mma(const __half* __restrict__ A, int lda,
           const __half* __restrict__ W, int ldw, int K,
           const float* __restrict__ P, float* __restrict__ dst,
           const float* __restrict__ bias, int M, int epi,
           const float* __restrict__ bn_g, const float* __restrict__ bn_b,
           const float* __restrict__ bn_m, const float* __restrict__ bn_v,
           __half* __restrict__ out_h) {
    extern __shared__ __half sm[];
    const uint32_t sb = smem_u32(sm);
    const uint32_t stb = (SA_BUF + SB_BUF) * 2;

    const int tid  = threadIdx.x;
    const int lane = tid & 31;
    const int warp = tid >> 5;
    const int wm   = (warp & 1) * 64;
    const int wn   = (warp >> 1) * 64;
    const int row0 = blockIdx.y * BM;
    const int col0 = blockIdx.x * BN;
    const int NIT  = K / BK;

    const int g = lane >> 2;
    const int c = lane & 3;

    const uint32_t a_off = (((lane & 15) * AST) + ((lane >> 4) * 8)) * 2;
    const uint32_t b_off = ((((lane & 7) + ((lane >> 4) << 3)) * AST)
                            + (((lane >> 3) & 1) * 8)) * 2;

    float acc[4][8][4];
    #pragma unroll
    for (int i = 0; i < 4; i++)
        #pragma unroll
        for (int j = 0; j < 8; j++) {
            acc[i][j][0] = 0.f; acc[i][j][1] = 0.f;
            acc[i][j][2] = 0.f; acc[i][j][3] = 0.f;
        }

    auto load_buf = [&](int it) {
        const int st = it % STAGES;
        const int k0 = it * BK;
        const uint32_t sA = sb + st * stb;
        const uint32_t sB = sA + SA_BUF * 2;
        #pragma unroll
        for (int i = 0; i < 2; i++) {
            int q = tid + i * 256;
            int r = q >> 2, ch = q & 3;
            int grow = row0 + r;
            const __half* src = A + (long long)(grow < M ? grow : M - 1) * lda + k0 + ch * 8;
            cp16(sA + (r * AST + ch * 8) * 2, src, (grow < M) ? 16 : 0);
        }
        #pragma unroll
        for (int i = 0; i < 4; i++) {
            int q = tid + i * 256;
            int r = q >> 2, ch = q & 3;
            const __half* src = W + (long long)(col0 + r) * ldw + k0 + ch * 8;
            cp16(sB + (r * AST + ch * 8) * 2, src, 16);
        }
        asm volatile("cp.async.commit_group;" ::: "memory");
    };

    load_buf(0);
    load_buf(1);

    for (int it = 0; it < NIT; it++) {
        if (it + 1 < NIT)
            asm volatile("cp.async.wait_group 1;" ::: "memory");
        else
            asm volatile("cp.async.wait_group 0;" ::: "memory");
        __syncthreads();
        if (it + 2 < NIT) load_buf(it + 2);

        const int st = it % STAGES;
        const uint32_t sA = sb + st * stb;
        const uint32_t sB = sA + SA_BUF * 2;

        #pragma unroll
        for (int ks = 0; ks < 2; ks++) {
            uint32_t af[4][4], bf[8][2];
            #pragma unroll
            for (int mt = 0; mt < 4; mt++)
                ldsm4(af[mt][0], af[mt][1], af[mt][2], af[mt][3],
                      sA + a_off + (uint32_t)((wm + mt * 16) * AST * 2) + ks * 32);
            #pragma unroll
            for (int p = 0; p < 4; p++)
                ldsm4(bf[2*p][0], bf[2*p][1], bf[2*p+1][0], bf[2*p+1][1],
                      sB + b_off + (uint32_t)((wn + p * 16) * AST * 2) + ks * 32);
            #pragma unroll
            for (int mt = 0; mt < 4; mt++)
                #pragma unroll
                for (int nt = 0; nt < 8; nt++)
                    mma16n8k16(acc[mt][nt], af[mt], bf[nt]);
        }
    }

    if (epi == 0) {
        // raw partial to dst (float)
        #pragma unroll
        for (int mt = 0; mt < 4; mt++) {
            int r0 = row0 + wm + mt * 16 + g;
            #pragma unroll
            for (int nt = 0; nt < 8; nt++) {
                int cc = col0 + wn + nt * 8 + c * 2;
                if (r0 < M)
                    *(float2*)&dst[(long long)r0 * 768 + cc] =
                        make_float2(acc[mt][nt][0], acc[mt][nt][1]);
                if (r0 + 8 < M)
                    *(float2*)&dst[(long long)(r0 + 8) * 768 + cc] =
                        make_float2(acc[mt][nt][2], acc[mt][nt][3]);
            }
        }
    } else if (epi == 1) {
        // P + bias + BN(eval) + ReLU -> half layer-2 A operand
        #pragma unroll
        for (int mt = 0; mt < 4; mt++) {
            int r0 = row0 + wm + mt * 16 + g;
            #pragma unroll
            for (int nt = 0; nt < 8; nt++) {
                int cc = col0 + wn + nt * 8 + c * 2;
                float2 b  = *(const float2*)&bias[cc];
                float2 gm = *(const float2*)&bn_g[cc];
                float2 bt = *(const float2*)&bn_b[cc];
                float2 mn = *(const float2*)&bn_m[cc];
                float2 vr = *(const float2*)&bn_v[cc];
                float s0 = rsqrtf(vr.x + 1e-5f) * gm.x;
                float s1 = rsqrtf(vr.y + 1e-5f) * gm.y;
                if (r0 < M) {
                    float2 p = *(const float2*)&P[(long long)r0 * 768 + cc];
                    float lo0 = fmaxf((acc[mt][nt][0] + p.x + b.x - mn.x) * s0 + bt.x, 0.f);
                    float lo1 = fmaxf((acc[mt][nt][1] + p.y + b.y - mn.y) * s1 + bt.y, 0.f);
                    *(__half2*)&out_h[(size_t)r0 * K2 + cc] = __floats2half2_rn(lo0, lo1);
                }
                if (r0 + 8 < M) {
                    float2 p = *(const float2*)&P[(long long)(r0 + 8) * 768 + cc];
                    float hi0 = fmaxf((acc[mt][nt][2] + p.x + b.x - mn.x) * s0 + bt.x, 0.f);
                    float hi1 = fmaxf((acc[mt][nt][3] + p.y + b.y - mn.y) * s1 + bt.y, 0.f);
                    *(__half2*)&out_h[(size_t)(r0 + 8) * K2 + cc] = __floats2half2_rn(hi0, hi1);
                }
            }
        }
    } else {
        // P + bias -> float dst (layer-2 final)
        #pragma unroll
        for (int mt = 0; mt < 4; mt++) {
            int r0 = row0 + wm + mt * 16 + g;
            #pragma unroll
            for (int nt = 0; nt < 8; nt++) {
                int cc = col0 + wn + nt * 8 + c * 2;
                float2 b = *(const float2*)&bias[cc];
                if (r0 < M) {
                    float2 p = *(const float2*)&P[(long long)r0 * 768 + cc];
                    *(float2*)&dst[(long long)r0 * 768 + cc] =
                        make_float2(acc[mt][nt][0] + p.x + b.x, acc[mt][nt][1] + p.y + b.y);
                }
                if (r0 + 8 < M) {
                    float2 p = *(const float2*)&P[(long long)(r0 + 8) * 768 + cc];
                    *(float2*)&dst[(long long)(r0 + 8) * 768 + cc] =
                        make_float2(acc[mt][nt][2] + p.x + b.x, acc[mt][nt][3] + p.y + b.y);
                }
            }
        }
    }
}

// ---------------- index-width detection (int32 vs int64 dump) ----------------
__global__ void k_detect(const int* ei) {
    __shared__ int found;
    if (threadIdx.x == 0) found = 0;
    __syncthreads();
    for (int i = threadIdx.x; i < 2048; i += blockDim.x)
        if (ei[2 * i + 1] != 0) found = 1;
    __syncthreads();
    if (threadIdx.x == 0) g_is64 = (found == 0) ? 1 : 0;
}
__device__ __forceinline__ int idx_at(const void* p, long long i, int is64) {
    return is64 ? (int)((const long long*)p)[i] : ((const int*)p)[i];
}

// ---------------- edge preprocessing / CSR build (scan-free) ----------------
__global__ void k_zero() {
    int i = blockIdx.x * blockDim.x + threadIdx.x;
    if (i < N_NODES * N_REL) g_cnt[i] = 0;
    if (i < N_NODES) g_deg[i] = 0;
    if (i == 0) g_total = 0;
}
__global__ void k_prep(const void* ei, const void* et) {
    int e = blockIdx.x * blockDim.x + threadIdx.x;
    if (e >= N_EDGES) return;
    int is64 = g_is64;
    int s = idx_at(ei, e, is64);
    int d = idx_at(ei, (long long)N_EDGES + e, is64);
    int t = idx_at(et, e, is64);
    g_esrc[e] = s; g_edst[e] = d; g_etyp[e] = t;
    atomicAdd(&g_cnt[d * N_REL + t], 1);
    atomicAdd(&g_deg[d], 1);
}
__global__ void k_alloc() {
    int i = blockIdx.x * blockDim.x + threadIdx.x;
    if (i >= N_NODES) return;
    g_off[i] = atomicAdd(&g_total, g_deg[i]);
    g_pos[i] = 0;
}
__global__ void k_fill() {
    int e = blockIdx.x * blockDim.x + threadIdx.x;
    if (e >= N_EDGES) return;
    int d = g_edst[e];
    int t = g_etyp[e];
    int p = atomicAdd(&g_pos[d], 1);
    float scl = 1.0f / (float)g_cnt[d * N_REL + t];
    g_es[g_off[d] + p] = make_int2(g_esrc[e] | (t << 20), __float_as_int(scl));
}

// ---------------- A conversion: x float -> g_A1[:, 0:256] half ---------------
__global__ void k_cvtA1(const float* __restrict__ x) {
    long long i = (long long)blockIdx.x * blockDim.x + threadIdx.x;  // half2 units
    if (i >= (long long)N_NODES * 128) return;
    int n  = (int)(i >> 7);
    int c2 = (int)(i & 127);
    float2 v = ((const float2*)x)[(long long)n * 128 + c2];
    *(__half2*)&g_A1[(size_t)n * K1 + c2 * 2] = __floats2half2_rn(v.x, v.y);
}

// ---------------- basis-combined CSR aggregation (unroll-2, MLP=2) -----------
__global__ void k_aggZ(__half* __restrict__ Abase, const float* __restrict__ comp,
                       int Fin, int K) {
    __shared__ float scomp[N_REL * N_BASES];
    int n = blockIdx.x;
    int tid = threadIdx.x;
    if (tid < N_REL * N_BASES) scomp[tid] = comp[tid];
    __syncthreads();
    int beg = g_off[n], deg = g_deg[n];
    float z0[4] = {}, z1[4] = {}, z2[4] = {}, z3[4] = {};
    int j = 0;
    for (; j + 2 <= deg; j += 2) {
        int2 m0 = g_es[beg + j];
        int2 m1 = g_es[beg + j + 1];
        int sA = m0.x & 0xFFFFF, tA = m0.x >> 20;
        int sB = m1.x & 0xFFFFF, tB = m1.x >> 20;
        const __half2* hA = (const __half2*)&Abase[(size_t)sA * K + tid * 4];
        const __half2* hB = (const __half2*)&Abase[(size_t)sB * K + tid * 4];
        float2 a0 = __half22float2(hA[0]);
        float2 a1 = __half22float2(hA[1]);
        float2 b0 = __half22float2(hB[0]);
        float2 b1 = __half22float2(hB[1]);
        float fA = __int_as_float(m0.y), fB = __int_as_float(m1.y);
        float cA0 = scomp[tA*4+0]*fA, cA1 = scomp[tA*4+1]*fA;
        float cA2 = scomp[tA*4+2]*fA, cA3 = scomp[tA*4+3]*fA;
        float cB0 = scomp[tB*4+0]*fB, cB1 = scomp[tB*4+1]*fB;
        float cB2 = scomp[tB*4+2]*fB, cB3 = scomp[tB*4+3]*fB;
        float vA[4] = { a0.x, a0.y, a1.x, a1.y };
        float vB[4] = { b0.x, b0.y, b1.x, b1.y };
        #pragma unroll
        for (int i = 0; i < 4; i++) {
            z0[i] = fmaf(vA[i], cA0, fmaf(vB[i], cB0, z0[i]));
            z1[i] = fmaf(vA[i], cA1, fmaf(vB[i], cB1, z1[i]));
            z2[i] = fmaf(vA[i], cA2, fmaf(vB[i], cB2, z2[i]));
            z3[i] = fmaf(vA[i], cA3, fmaf(vB[i], cB3, z3[i]));
        }
    }
    if (j < deg) {
        int2 m0 = g_es[beg + j];
        int sA = m0.x & 0xFFFFF, tA = m0.x >> 20;
        const __half2* hA = (const __half2*)&Abase[(size_t)sA * K + tid * 4];
        float2 a0 = __half22float2(hA[0]);
        float2 a1 = __half22float2(hA[1]);
        float fA = __int_as_float(m0.y);
        float cA0 = scomp[tA*4+0]*fA, cA1 = scomp[tA*4+1]*fA;
        float cA2 = scomp[tA*4+2]*fA, cA3 = scomp[tA*4+3]*fA;
        float vA[4] = { a0.x, a0.y, a1.x, a1.y };
        #pragma unroll
        for (int i = 0; i < 4; i++) {
            z0[i] = fmaf(vA[i], cA0, z0[i]);
            z1[i] = fmaf(vA[i], cA1, z1[i]);
            z2[i] = fmaf(vA[i], cA2, z2[i]);
            z3[i] = fmaf(vA[i], cA3, z3[i]);
        }
    }
    __half2* d0 = (__half2*)&Abase[(size_t)n * K + Fin * 1 + tid * 4];
    __half2* d1 = (__half2*)&Abase[(size_t)n * K + Fin * 2 + tid * 4];
    __half2* d2 = (__half2*)&Abase[(size_t)n * K + Fin * 3 + tid * 4];
    __half2* d3 = (__half2*)&Abase[(size_t)n * K + Fin * 4 + tid * 4];
    d0[0] = __floats2half2_rn(z0[0], z0[1]); d0[1] = __floats2half2_rn(z0[2], z0[3]);
    d1[0] = __floats2half2_rn(z1[0], z1[1]); d1[1] = __floats2half2_rn(z1[2], z1[3]);
    d2[0] = __floats2half2_rn(z2[0], z2[1]); d2[1] = __floats2half2_rn(z2[2], z2[3]);
    d3[0] = __floats2half2_rn(z3[0], z3[1]); d3[1] = __floats2half2_rn(z3[2], z3[3]);
}

// ---------------- weight build: W[j, kidx] (K-major), j<768 ------------------
__global__ void k_buildW(const float* __restrict__ root,
                         const float* __restrict__ basis, int Fin, int K,
                         __half* __restrict__ W) {
    long long i = (long long)blockIdx.x * blockDim.x + threadIdx.x;
    long long tot = (long long)768 * K;
    if (i >= tot) return;
    int j = (int)(i / K), kidx = (int)(i % K);
    float v;
    if (kidx < Fin) {
        v = root[(long long)kidx * 768 + j];
    } else {
        int t = kidx - Fin;
        int b = t / Fin, k = t % Fin;
        v = basis[((long long)b * Fin + k) * 768 + j];
    }
    W[i] = __float2half_rn(v);
}

// ---------------- L2 normalize ----------------
__global__ void k_l2norm(float* __restrict__ out) {
    int n = blockIdx.x;
    float4 v = *(float4*)&out[(long long)n * 768 + threadIdx.x * 4];
    float ss = v.x*v.x + v.y*v.y + v.z*v.z + v.w*v.w;
    #pragma unroll
    for (int o = 16; o > 0; o >>= 1)
        ss += __shfl_xor_sync(0xffffffffu, ss, o);
    __shared__ float sw[6];
    __shared__ float s_inv;
    int wid = threadIdx.x / 32;
    if ((threadIdx.x & 31) == 0) sw[wid] = ss;
    __syncthreads();
    if (threadIdx.x == 0) {
        float tot = sw[0] + sw[1] + sw[2] + sw[3] + sw[4] + sw[5];
        s_inv = 1.0f / fmaxf(sqrtf(tot), 1e-12f);
    }
    __syncthreads();
    float inv = s_inv;
    v.x *= inv; v.y *= inv; v.z *= inv; v.w *= inv;
    *(float4*)&out[(long long)n * 768 + threadIdx.x * 4] = v;
}

// ---------------- launch ----------------
extern "C" void kernel_launch(void* const* d_in, const int* in_sizes, int n_in,
                              void* d_out, int out_size) {
    const float* x       = (const float*)d_in[0];
    const void*  ei      = d_in[1];
    const void*  et      = d_in[2];
    const float* basis1  = (const float*)d_in[3];
    const float* comp1   = (const float*)d_in[4];
    const float* root1   = (const float*)d_in[5];
    const float* bias1   = (const float*)d_in[6];
    const float* bn_g    = (const float*)d_in[7];
    const float* bn_b    = (const float*)d_in[8];
    const float* bn_m    = (const float*)d_in[9];
    const float* bn_v    = (const float*)d_in[10];
    const float* basis2  = (const float*)d_in[11];
    const float* comp2   = (const float*)d_in[12];
    const float* root2   = (const float*)d_in[13];
    const float* bias2   = (const float*)d_in[14];
    float* out = (float*)d_out;

    __half* g_A1_p;  cudaGetSymbolAddress((void**)&g_A1_p,  g_A1);
    __half* g_A2_p;  cudaGetSymbolAddress((void**)&g_A2_p,  g_A2);
    __half* g_W1_p;  cudaGetSymbolAddress((void**)&g_W1_p,  g_Wh1);
    __half* g_W2_p;  cudaGetSymbolAddress((void**)&g_W2_p,  g_Wh2);
    float*  g_P_p;   cudaGetSymbolAddress((void**)&g_P_p,   g_P);

    cudaFuncSetAttribute(k_gemm_mma, cudaFuncAttributeMaxDynamicSharedMemorySize, SM_TOTAL);

    const int EB = (N_EDGES + 255) / 256;
    dim3 gemm_grid(768 / BN, (N_NODES + BM - 1) / BM);

    cudaStream_t s1;
    cudaEvent_t evF, evC, evG1a, evL1, evG2a;
    cudaStreamCreateWithFlags(&s1, cudaStreamNonBlocking);
    cudaEventCreateWithFlags(&evF,   cudaEventDisableTiming);
    cudaEventCreateWithFlags(&evC,   cudaEventDisableTiming);
    cudaEventCreateWithFlags(&evG1a, cudaEventDisableTiming);
    cudaEventCreateWithFlags(&evL1,  cudaEventDisableTiming);
    cudaEventCreateWithFlags(&evG2a, cudaEventDisableTiming);

    k_detect<<<1, 256>>>((const int*)ei);
    cudaEventRecord(evF, 0);
    cudaStreamWaitEvent(s1, evF, 0);

    // ---- branch s1: params + features + partial GEMM1a ----
    k_cvtA1<<<(int)(((long long)N_NODES * 128 + 255) / 256), 256, 0, s1>>>(x);
    cudaEventRecord(evC, s1);                      // g_A1 features ready
    k_buildW<<<(int)(((long long)768 * K1 + 255) / 256), 256, 0, s1>>>(root1, basis1, IN_CH, K1, g_W1_p);
    k_gemm_mma<<<gemm_grid, 256, SM_TOTAL, s1>>>(g_A1_p, K1, g_W1_p, K1, IN_CH,
                                                 nullptr, g_P_p, nullptr, N_NODES, 0,
                                                 nullptr, nullptr, nullptr, nullptr, nullptr);
    k_buildW<<<(int)(((long long)768 * K2 + 255) / 256), 256, 0, s1>>>(root2, basis2, HID, K2, g_W2_p);
    cudaEventRecord(evG1a, s1);

    // ---- branch 0: edge preprocessing + CSR + aggZ1 ----
    k_zero<<<(N_NODES * N_REL + 255) / 256, 256>>>();
    k_prep<<<EB, 256>>>(ei, et);
    k_alloc<<<(N_NODES + 255) / 256, 256>>>();
    k_fill<<<EB, 256>>>();
    cudaStreamWaitEvent(0, evC, 0);
    k_aggZ<<<N_NODES, IN_CH / 4>>>(g_A1_p, comp1, IN_CH, K1);

    // ---- join: GEMM1b (Z part, K=1024) accumulates g_P, BN+ReLU -> g_A2 ----
    cudaStreamWaitEvent(0, evG1a, 0);
    k_gemm_mma<<<gemm_grid, 256, SM_TOTAL>>>(g_A1_p + IN_CH, K1, g_W1_p + IN_CH, K1, 4 * IN_CH,
                                             g_P_p, nullptr, bias1, N_NODES, 1,
                                             bn_g, bn_b, bn_m, bn_v, g_A2_p);
    cudaEventRecord(evL1, 0);

    // ---- layer 2 fork: GEMM2a (features, K=768) on s1, aggZ2 on 0 ----
    cudaStreamWaitEvent(s1, evL1, 0);
    k_gemm_mma<<<gemm_grid, 256, SM_TOTAL, s1>>>(g_A2_p, K2, g_W2_p, K2, HID,
                                                 nullptr, g_P_p, nullptr, N_NODES, 0,
                                                 nullptr, nullptr, nullptr, nullptr, nullptr);
    cudaEventRecord(evG2a, s1);
    k_aggZ<<<N_NODES, HID / 4>>>(g_A2_p, comp2, HID, K2);

    // ---- join: GEMM2b (Z part, K=3072) accumulates g_P + bias -> out ----
    cudaStreamWaitEvent(0, evG2a, 0);
    k_gemm_mma<<<gemm_grid, 256, SM_TOTAL>>>(g_A2_p + HID, K2, g_W2_p + HID, K2, 4 * HID,
                                             g_P_p, out, bias2, N_NODES, 2,
                                             nullptr, nullptr, nullptr, nullptr, nullptr);
    k_l2norm<<<N_NODES, 192>>>(out);

    cudaStreamDestroy(s1);
    cudaEventDestroy(evF);
    cudaEventDestroy(evC);
    cudaEventDestroy(evG1a);
    cudaEventDestroy(evL1);
    cudaEventDestroy(evG2a);
}

// round 11
// speedup vs baseline: 1.0746x; 1.0746x over previous
#include <cuda_runtime.h>
#include <cuda_fp16.h>
#include <cstdint>
#include <math.h>

#define N_NODES 50000
#define N_EDGES 200000
#define IN_CH   256
#define HID     768
#define N_REL   5
#define N_BASES 4
#define K1      (5*IN_CH)   /* 1280: [x | Z0..Z3] layer 1 */
#define K2      (5*HID)     /* 3840: [h | Z0..Z3] layer 2 */

// ---------------- static device scratch (no allocations allowed) -------------
__device__ __half g_A1[(size_t)N_NODES * K1];   // layer-1 GEMM A operand (122 MB)
__device__ __half g_A2[(size_t)N_NODES * K2];   // layer-2 GEMM A operand (366 MB)
__device__ __half g_Wh1[(size_t)HID * K1];      // layer-1 B^T (K-major, half)
__device__ __half g_Wh2[(size_t)HID * K2];      // layer-2 B^T (K-major, half)
__device__ int    g_cnt[N_NODES * N_REL];
__device__ int    g_deg[N_NODES];
__device__ int    g_off[N_NODES];
__device__ int    g_pos[N_NODES];
__device__ int2   g_es[N_EDGES];                // per-slot {src|(t<<20), bits(1/cnt)}
__device__ int    g_esrc[N_EDGES];
__device__ int    g_edst[N_EDGES];
__device__ int    g_etyp[N_EDGES];
__device__ int    g_total;
__device__ int    g_is64;

// ============================ helpers ====================================
__device__ __forceinline__ void cp16(uint32_t dst, const void* src, int sz) {
    asm volatile("cp.async.cg.shared.global [%0], [%1], 16, %2;"
                 :: "r"(dst), "l"(src), "r"(sz));
}
__device__ __forceinline__ uint32_t smem_u32(const void* p) {
    uint32_t a;
    asm("{ .reg .u64 t; cvta.to.shared.u64 t, %1; cvt.u32.u64 %0, t; }"
        : "=r"(a) : "l"(p));
    return a;
}
__device__ __forceinline__ void mma16n8k16(float* d, const uint32_t* a, const uint32_t* b) {
    asm volatile(
        "mma.sync.aligned.m16n8k16.row.col.f32.f16.f16.f32 "
        "{%0,%1,%2,%3}, {%4,%5,%6,%7}, {%8,%9}, {%0,%1,%2,%3};"
        : "+f"(d[0]), "+f"(d[1]), "+f"(d[2]), "+f"(d[3])
        : "r"(a[0]), "r"(a[1]), "r"(a[2]), "r"(a[3]), "r"(b[0]), "r"(b[1]));
}
__device__ __forceinline__ void ldsm4(uint32_t& r0, uint32_t& r1, uint32_t& r2,
                                      uint32_t& r3, uint32_t addr) {
    asm volatile("ldmatrix.sync.aligned.m8n8.x4.shared.b16 {%0,%1,%2,%3}, [%4];"
                 : "=r"(r0), "=r"(r1), "=r"(r2), "=r"(r3) : "r"(addr));
}

// ====================== fp16 mma.sync GEMM (fp32 accum) ======================
// out = A[M, K] @ W^T + bias   (W is [768, K] K-major, half)
// epi=0: float out to dst[M,768].  epi=1: BN(eval)+ReLU, half out to
//        out_h[row*K2 + col] (layer-2 A operand feature block).
#define BM 128
#define BN 256
#define BK 32
#define AST 40                              /* padded row stride in halves */
#define SA_BUF (BM * AST)
#define SB_BUF (BN * AST)
#define STAGES 3
#define SM_TOTAL (STAGES * (SA_BUF + SB_BUF) * 2)   /* 92160 bytes */

__global__ void __launch_bounds__(256, 1)
k_gemm_mma(const __half* __restrict__ A, const __half* __restrict__ W,
           float* __restrict__ dst, const float* __restrict__ bias,
           int M, int K, int epi,
           const float* __restrict__ bn_g, const float* __restrict__ bn_b,
           const float* __restrict__ bn_m, const float* __restrict__ bn_v,
           __half* __restrict__ out_h) {
    extern __shared__ __half sm[];
    const uint32_t sb = smem_u32(sm);
    const uint32_t stb = (SA_BUF + SB_BUF) * 2;

    const int tid  = threadIdx.x;
    const int lane = tid & 31;
    const int warp = tid >> 5;
    const int wm   = (warp & 1) * 64;
    const int wn   = (warp >> 1) * 64;
    const int row0 = blockIdx.y * BM;
    const int col0 = blockIdx.x * BN;
    const int NIT  = K / BK;

    const int g = lane >> 2;
    const int c = lane & 3;

    const uint32_t a_off = (((lane & 15) * AST) + ((lane >> 4) * 8)) * 2;
    const uint32_t b_off = ((((lane & 7) + ((lane >> 4) << 3)) * AST)
                            + (((lane >> 3) & 1) * 8)) * 2;

    float acc[4][8][4];
    #pragma unroll
    for (int i = 0; i < 4; i++)
        #pragma unroll
        for (int j = 0; j < 8; j++) {
            acc[i][j][0] = 0.f; acc[i][j][1] = 0.f;
            acc[i][j][2] = 0.f; acc[i][j][3] = 0.f;
        }

    auto load_buf = [&](int it) {
        const int st = it % STAGES;
        const int k0 = it * BK;
        const uint32_t sA = sb + st * stb;
        const uint32_t sB = sA + SA_BUF * 2;
        #pragma unroll
        for (int i = 0; i < 2; i++) {
            int q = tid + i * 256;
            int r = q >> 2, ch = q & 3;
            int grow = row0 + r;
            const __half* src = A + (long long)(grow < M ? grow : M - 1) * K + k0 + ch * 8;
            cp16(sA + (r * AST + ch * 8) * 2, src, (grow < M) ? 16 : 0);
        }
        #pragma unroll
        for (int i = 0; i < 4; i++) {
            int q = tid + i * 256;
            int r = q >> 2, ch = q & 3;
            const __half* src = W + (long long)(col0 + r) * K + k0 + ch * 8;
            cp16(sB + (r * AST + ch * 8) * 2, src, 16);
        }
        asm volatile("cp.async.commit_group;" ::: "memory");
    };

    load_buf(0);
    load_buf(1);

    for (int it = 0; it < NIT; it++) {
        if (it + 1 < NIT)
            asm volatile("cp.async.wait_group 1;" ::: "memory");
        else
            asm volatile("cp.async.wait_group 0;" ::: "memory");
        __syncthreads();
        if (it + 2 < NIT) load_buf(it + 2);

        const int st = it % STAGES;
        const uint32_t sA = sb + st * stb;
        const uint32_t sB = sA + SA_BUF * 2;

        #pragma unroll
        for (int ks = 0; ks < 2; ks++) {
            uint32_t af[4][4], bf[8][2];
            #pragma unroll
            for (int mt = 0; mt < 4; mt++)
                ldsm4(af[mt][0], af[mt][1], af[mt][2], af[mt][3],
                      sA + a_off + (uint32_t)((wm + mt * 16) * AST * 2) + ks * 32);
            #pragma unroll
            for (int p = 0; p < 4; p++)
                ldsm4(bf[2*p][0], bf[2*p][1], bf[2*p+1][0], bf[2*p+1][1],
                      sB + b_off + (uint32_t)((wn + p * 16) * AST * 2) + ks * 32);
            #pragma unroll
            for (int mt = 0; mt < 4; mt++)
                #pragma unroll
                for (int nt = 0; nt < 8; nt++)
                    mma16n8k16(acc[mt][nt], af[mt], bf[nt]);
        }
    }

    if (epi == 0) {
        #pragma unroll
        for (int mt = 0; mt < 4; mt++) {
            int r0 = row0 + wm + mt * 16 + g;
            #pragma unroll
            for (int nt = 0; nt < 8; nt++) {
                int cc = col0 + wn + nt * 8 + c * 2;
                float2 b = *(const float2*)&bias[cc];
                if (r0 < M)
                    *(float2*)&dst[(long long)r0 * 768 + cc] =
                        make_float2(acc[mt][nt][0] + b.x, acc[mt][nt][1] + b.y);
                if (r0 + 8 < M)
                    *(float2*)&dst[(long long)(r0 + 8) * 768 + cc] =
                        make_float2(acc[mt][nt][2] + b.x, acc[mt][nt][3] + b.y);
            }
        }
    } else {
        // fused bias + BN(eval) + ReLU, half output to layer-2 A operand
        #pragma unroll
        for (int mt = 0; mt < 4; mt++) {
            int r0 = row0 + wm + mt * 16 + g;
            #pragma unroll
            for (int nt = 0; nt < 8; nt++) {
                int cc = col0 + wn + nt * 8 + c * 2;
                float2 b  = *(const float2*)&bias[cc];
                float2 gm = *(const float2*)&bn_g[cc];
                float2 bt = *(const float2*)&bn_b[cc];
                float2 mn = *(const float2*)&bn_m[cc];
                float2 vr = *(const float2*)&bn_v[cc];
                float s0 = rsqrtf(vr.x + 1e-5f) * gm.x;
                float s1 = rsqrtf(vr.y + 1e-5f) * gm.y;
                float lo0 = fmaxf((acc[mt][nt][0] + b.x - mn.x) * s0 + bt.x, 0.f);
                float lo1 = fmaxf((acc[mt][nt][1] + b.y - mn.y) * s1 + bt.y, 0.f);
                float hi0 = fmaxf((acc[mt][nt][2] + b.x - mn.x) * s0 + bt.x, 0.f);
                float hi1 = fmaxf((acc[mt][nt][3] + b.y - mn.y) * s1 + bt.y, 0.f);
                if (r0 < M)
                    *(__half2*)&out_h[(size_t)r0 * K2 + cc] = __floats2half2_rn(lo0, lo1);
                if (r0 + 8 < M)
                    *(__half2*)&out_h[(size_t)(r0 + 8) * K2 + cc] = __floats2half2_rn(hi0, hi1);
            }
        }
    }
}

// ---------------- index-width detection (int32 vs int64 dump) ----------------
__global__ void k_detect(const int* ei) {
    __shared__ int found;
    if (threadIdx.x == 0) found = 0;
    __syncthreads();
    for (int i = threadIdx.x; i < 2048; i += blockDim.x)
        if (ei[2 * i + 1] != 0) found = 1;
    __syncthreads();
    if (threadIdx.x == 0) g_is64 = (found == 0) ? 1 : 0;
}
__device__ __forceinline__ int idx_at(const void* p, long long i, int is64) {
    return is64 ? (int)((const long long*)p)[i] : ((const int*)p)[i];
}

// ---------------- edge preprocessing / CSR build (scan-free) ----------------
__global__ void k_zero() {
    int i = blockIdx.x * blockDim.x + threadIdx.x;
    if (i < N_NODES * N_REL) g_cnt[i] = 0;
    if (i < N_NODES) g_deg[i] = 0;
    if (i == 0) g_total = 0;
}
__global__ void k_prep(const void* ei, const void* et) {
    int e = blockIdx.x * blockDim.x + threadIdx.x;
    if (e >= N_EDGES) return;
    int is64 = g_is64;
    int s = idx_at(ei, e, is64);
    int d = idx_at(ei, (long long)N_EDGES + e, is64);
    int t = idx_at(et, e, is64);
    g_esrc[e] = s; g_edst[e] = d; g_etyp[e] = t;
    atomicAdd(&g_cnt[d * N_REL + t], 1);
    atomicAdd(&g_deg[d], 1);
}
__global__ void k_alloc() {
    int i = blockIdx.x * blockDim.x + threadIdx.x;
    if (i >= N_NODES) return;
    g_off[i] = atomicAdd(&g_total, g_deg[i]);
    g_pos[i] = 0;
}
__global__ void k_fill() {
    int e = blockIdx.x * blockDim.x + threadIdx.x;
    if (e >= N_EDGES) return;
    int d = g_edst[e];
    int t = g_etyp[e];
    int p = atomicAdd(&g_pos[d], 1);
    float scl = 1.0f / (float)g_cnt[d * N_REL + t];
    g_es[g_off[d] + p] = make_int2(g_esrc[e] | (t << 20), __float_as_int(scl));
}

// ---------------- A conversion: x float -> g_A1[:, 0:256] half ---------------
__global__ void k_cvtA1(const float* __restrict__ x) {
    long long i = (long long)blockIdx.x * blockDim.x + threadIdx.x;  // half2 units
    if (i >= (long long)N_NODES * 128) return;
    int n  = (int)(i >> 7);
    int c2 = (int)(i & 127);
    float2 v = ((const float2*)x)[(long long)n * 128 + c2];
    *(__half2*)&g_A1[(size_t)n * K1 + c2 * 2] = __floats2half2_rn(v.x, v.y);
}

// ---------------- basis-combined CSR aggregation (unroll-4, MLP=4) -----------
// One block per dst node, Fin/4 threads. Z_b[n] = sum_edges comp[t,b]/cnt * A[src]
__global__ void k_aggZ(__half* __restrict__ Abase, const float* __restrict__ comp,
                       int Fin, int K) {
    __shared__ float scomp[N_REL * N_BASES];
    int n = blockIdx.x;
    int tid = threadIdx.x;
    if (tid < N_REL * N_BASES) scomp[tid] = comp[tid];
    __syncthreads();
    int beg = g_off[n], deg = g_deg[n];
    float z0[4] = {}, z1[4] = {}, z2[4] = {}, z3[4] = {};
    int j = 0;
    for (; j + 4 <= deg; j += 4) {
        int2 m[4];
        #pragma unroll
        for (int q = 0; q < 4; q++) m[q] = g_es[beg + j + q];
        const __half2* h[4];
        #pragma unroll
        for (int q = 0; q < 4; q++)
            h[q] = (const __half2*)&Abase[(size_t)(m[q].x & 0xFFFFF) * K + tid * 4];
        #pragma unroll
        for (int q = 0; q < 4; q++) {
            int t = m[q].x >> 20;
            float f = __int_as_float(m[q].y);
            float c0 = scomp[t*4+0]*f, c1 = scomp[t*4+1]*f;
            float c2 = scomp[t*4+2]*f, c3 = scomp[t*4+3]*f;
            float2 a0 = __half22float2(h[q][0]);
            float2 a1 = __half22float2(h[q][1]);
            float v[4] = { a0.x, a0.y, a1.x, a1.y };
            #pragma unroll
            for (int i = 0; i < 4; i++) {
                z0[i] = fmaf(v[i], c0, z0[i]);
                z1[i] = fmaf(v[i], c1, z1[i]);
                z2[i] = fmaf(v[i], c2, z2[i]);
                z3[i] = fmaf(v[i], c3, z3[i]);
            }
        }
    }
    for (; j < deg; j++) {
        int2 m0 = g_es[beg + j];
        int sA = m0.x & 0xFFFFF, tA = m0.x >> 20;
        const __half2* hA = (const __half2*)&Abase[(size_t)sA * K + tid * 4];
        float2 a0 = __half22float2(hA[0]);
        float2 a1 = __half22float2(hA[1]);
        float fA = __int_as_float(m0.y);
        float cA0 = scomp[tA*4+0]*fA, cA1 = scomp[tA*4+1]*fA;
        float cA2 = scomp[tA*4+2]*fA, cA3 = scomp[tA*4+3]*fA;
        float vA[4] = { a0.x, a0.y, a1.x, a1.y };
        #pragma unroll
        for (int i = 0; i < 4; i++) {
            z0[i] = fmaf(vA[i], cA0, z0[i]);
            z1[i] = fmaf(vA[i], cA1, z1[i]);
            z2[i] = fmaf(vA[i], cA2, z2[i]);
            z3[i] = fmaf(vA[i], cA3, z3[i]);
        }
    }
    __half2* d0 = (__half2*)&Abase[(size_t)n * K + Fin * 1 + tid * 4];
    __half2* d1 = (__half2*)&Abase[(size_t)n * K + Fin * 2 + tid * 4];
    __half2* d2 = (__half2*)&Abase[(size_t)n * K + Fin * 3 + tid * 4];
    __half2* d3 = (__half2*)&Abase[(size_t)n * K + Fin * 4 + tid * 4];
    d0[0] = __floats2half2_rn(z0[0], z0[1]); d0[1] = __floats2half2_rn(z0[2], z0[3]);
    d1[0] = __floats2half2_rn(z1[0], z1[1]); d1[1] = __floats2half2_rn(z1[2], z1[3]);
    d2[0] = __floats2half2_rn(z2[0], z2[1]); d2[1] = __floats2half2_rn(z2[2], z2[3]);
    d3[0] = __floats2half2_rn(z3[0], z3[1]); d3[1] = __floats2half2_rn(z3[2], z3[3]);
}

// ---------------- weight build: W[j, kidx] (K-major), j<768 ------------------
__global__ void k_buildW(const float* __restrict__ root,
                         const float* __restrict__ basis, int Fin, int K,
                         __half* __restrict__ W) {
    long long i = (long long)blockIdx.x * blockDim.x + threadIdx.x;
    long long tot = (long long)768 * K;
    if (i >= tot) return;
    int j = (int)(i / K), kidx = (int)(i % K);
    float v;
    if (kidx < Fin) {
        v = root[(long long)kidx * 768 + j];
    } else {
        int t = kidx - Fin;
        int b = t / Fin, k = t % Fin;
        v = basis[((long long)b * Fin + k) * 768 + j];
    }
    W[i] = __float2half_rn(v);
}

// ---------------- L2 normalize ----------------
__global__ void k_l2norm(float* __restrict__ out) {
    int n = blockIdx.x;
    float4 v = *(float4*)&out[(long long)n * 768 + threadIdx.x * 4];
    float ss = v.x*v.x + v.y*v.y + v.z*v.z + v.w*v.w;
    #pragma unroll
    for (int o = 16; o > 0; o >>= 1)
        ss += __shfl_xor_sync(0xffffffffu, ss, o);
    __shared__ float sw[6];
    __shared__ float s_inv;
    int wid = threadIdx.x / 32;
    if ((threadIdx.x & 31) == 0) sw[wid] = ss;
    __syncthreads();
    if (threadIdx.x == 0) {
        float tot = sw[0] + sw[1] + sw[2] + sw[3] + sw[4] + sw[5];
        s_inv = 1.0f / fmaxf(sqrtf(tot), 1e-12f);
    }
    __syncthreads();
    float inv = s_inv;
    v.x *= inv; v.y *= inv; v.z *= inv; v.w *= inv;
    *(float4*)&out[(long long)n * 768 + threadIdx.x * 4] = v;
}

// ---------------- launch ----------------
extern "C" void kernel_launch(void* const* d_in, const int* in_sizes, int n_in,
                              void* d_out, int out_size) {
    const float* x       = (const float*)d_in[0];
    const void*  ei      = d_in[1];
    const void*  et      = d_in[2];
    const float* basis1  = (const float*)d_in[3];
    const float* comp1   = (const float*)d_in[4];
    const float* root1   = (const float*)d_in[5];
    const float* bias1   = (const float*)d_in[6];
    const float* bn_g    = (const float*)d_in[7];
    const float* bn_b    = (const float*)d_in[8];
    const float* bn_m    = (const float*)d_in[9];
    const float* bn_v    = (const float*)d_in[10];
    const float* basis2  = (const float*)d_in[11];
    const float* comp2   = (const float*)d_in[12];
    const float* root2   = (const float*)d_in[13];
    const float* bias2   = (const float*)d_in[14];
    float* out = (float*)d_out;

    __half* g_A1_p;  cudaGetSymbolAddress((void**)&g_A1_p,  g_A1);
    __half* g_A2_p;  cudaGetSymbolAddress((void**)&g_A2_p,  g_A2);
    __half* g_W1_p;  cudaGetSymbolAddress((void**)&g_W1_p,  g_Wh1);
    __half* g_W2_p;  cudaGetSymbolAddress((void**)&g_W2_p,  g_Wh2);

    cudaFuncSetAttribute(k_gemm_mma, cudaFuncAttributeMaxDynamicSharedMemorySize, SM_TOTAL);

    const int EB = (N_EDGES + 255) / 256;
    dim3 gemm_grid(768 / BN, (N_NODES + BM - 1) / BM);

    cudaStream_t s1;
    cudaEvent_t evF, evC, evW1, evW2;
    cudaStreamCreateWithFlags(&s1, cudaStreamNonBlocking);
    cudaEventCreateWithFlags(&evF,  cudaEventDisableTiming);
    cudaEventCreateWithFlags(&evC,  cudaEventDisableTiming);
    cudaEventCreateWithFlags(&evW1, cudaEventDisableTiming);
    cudaEventCreateWithFlags(&evW2, cudaEventDisableTiming);

    k_detect<<<1, 256>>>((const int*)ei);
    cudaEventRecord(evF, 0);
    cudaStreamWaitEvent(s1, evF, 0);

    // ---- branch s1: features first (unblocks aggZ1 asap), then weights ----
    k_cvtA1<<<(int)(((long long)N_NODES * 128 + 255) / 256), 256, 0, s1>>>(x);
    cudaEventRecord(evC, s1);
    k_buildW<<<(int)(((long long)768 * K1 + 255) / 256), 256, 0, s1>>>(root1, basis1, IN_CH, K1, g_W1_p);
    cudaEventRecord(evW1, s1);
    k_buildW<<<(int)(((long long)768 * K2 + 255) / 256), 256, 0, s1>>>(root2, basis2, HID, K2, g_W2_p);
    cudaEventRecord(evW2, s1);

    // ---- branch 0: edge preprocessing + CSR build ----
    k_zero<<<(N_NODES * N_REL + 255) / 256, 256>>>();
    k_prep<<<EB, 256>>>(ei, et);
    k_alloc<<<(N_NODES + 255) / 256, 256>>>();
    k_fill<<<EB, 256>>>();

    // aggZ1 needs only cvtA1 + fill (buildW2 still running concurrently)
    cudaStreamWaitEvent(0, evC, 0);
    k_aggZ<<<N_NODES, IN_CH / 4>>>(g_A1_p, comp1, IN_CH, K1);

    // ---- layer 1 GEMM (needs buildW1; epilogue: bias + BN + ReLU -> g_A2) ----
    cudaStreamWaitEvent(0, evW1, 0);
    k_gemm_mma<<<gemm_grid, 256, SM_TOTAL>>>(g_A1_p, g_W1_p, nullptr, bias1, N_NODES, K1, 1,
                                             bn_g, bn_b, bn_m, bn_v, g_A2_p);

    // ---- layer 2 ----
    k_aggZ<<<N_NODES, HID / 4>>>(g_A2_p, comp2, HID, K2);
    cudaStreamWaitEvent(0, evW2, 0);
    k_gemm_mma<<<gemm_grid, 256, SM_TOTAL>>>(g_A2_p, g_W2_p, out, bias2, N_NODES, K2, 0,
                                             nullptr, nullptr, nullptr, nullptr, nullptr);
    k_l2norm<<<N_NODES, 192>>>(out);

    cudaStreamDestroy(s1);
    cudaEventDestroy(evF);
    cudaEventDestroy(evC);
    cudaEventDestroy(evW1);
    cudaEventDestroy(evW2);
}

// round 12
// speedup vs baseline: 1.1056x; 1.0289x over previous
#include <cuda_runtime.h>
#include <cuda_fp16.h>
#include <cstdint>
#include <math.h>

#define N_NODES 50000
#define N_EDGES 200000
#define IN_CH   256
#define HID     768
#define N_REL   5
#define N_BASES 4
#define K1      (5*IN_CH)   /* 1280: [x | Z0..Z3] layer 1 */
#define K2      (5*HID)     /* 3840: [h | Z0..Z3] layer 2 */

// ---------------- static device scratch (no allocations allowed) -------------
__device__ __half g_A1[(size_t)N_NODES * K1];   // layer-1 GEMM A operand (122 MB)
__device__ __half g_A2[(size_t)N_NODES * K2];   // layer-2 GEMM A operand (366 MB)
__device__ __half g_Wh1[(size_t)HID * K1];      // layer-1 B^T (K-major, half)
__device__ __half g_Wh2[(size_t)HID * K2];      // layer-2 B^T (K-major, half)
__device__ int    g_cnt[N_NODES * N_REL];
__device__ int    g_deg[N_NODES];
__device__ int    g_off[N_NODES];
__device__ int    g_pos[N_NODES];
__device__ int2   g_es[N_EDGES];                // per-slot {src|(t<<20), bits(1/cnt)}
__device__ int    g_esrc[N_EDGES];
__device__ int    g_edst[N_EDGES];
__device__ int    g_etyp[N_EDGES];
__device__ int    g_total;
__device__ int    g_is64;

// ============================ helpers ====================================
__device__ __forceinline__ void cp16(uint32_t dst, const void* src, int sz) {
    asm volatile("cp.async.cg.shared.global [%0], [%1], 16, %2;"
                 :: "r"(dst), "l"(src), "r"(sz));
}
__device__ __forceinline__ uint32_t smem_u32(const void* p) {
    uint32_t a;
    asm("{ .reg .u64 t; cvta.to.shared.u64 t, %1; cvt.u32.u64 %0, t; }"
        : "=r"(a) : "l"(p));
    return a;
}
__device__ __forceinline__ void mma16n8k16(float* d, const uint32_t* a, const uint32_t* b) {
    asm volatile(
        "mma.sync.aligned.m16n8k16.row.col.f32.f16.f16.f32 "
        "{%0,%1,%2,%3}, {%4,%5,%6,%7}, {%8,%9}, {%0,%1,%2,%3};"
        : "+f"(d[0]), "+f"(d[1]), "+f"(d[2]), "+f"(d[3])
        : "r"(a[0]), "r"(a[1]), "r"(a[2]), "r"(a[3]), "r"(b[0]), "r"(b[1]));
}
__device__ __forceinline__ void ldsm4(uint32_t& r0, uint32_t& r1, uint32_t& r2,
                                      uint32_t& r3, uint32_t addr) {
    asm volatile("ldmatrix.sync.aligned.m8n8.x4.shared.b16 {%0,%1,%2,%3}, [%4];"
                 : "=r"(r0), "=r"(r1), "=r"(r2), "=r"(r3) : "r"(addr));
}

// ====================== fp16 mma.sync GEMM (fp32 accum) ======================
// out = A[M, K] @ W^T + bias   (W is [768, K] K-major, half)
// epi=0: float out to dst[M,768].  epi=1: BN(eval)+ReLU, half out to
//        out_h[row*K2 + col] (layer-2 A operand feature block).
#define BM 128
#define BN 256
#define BK 32
#define AST 40                              /* padded row stride in halves */
#define SA_BUF (BM * AST)
#define SB_BUF (BN * AST)
#define STAGES 3
#define SM_TOTAL (STAGES * (SA_BUF + SB_BUF) * 2)   /* 92160 bytes */

__global__ void __launch_bounds__(256, 1)
k_gemm_mma(const __half* __restrict__ A, const __half* __restrict__ W,
           float* __restrict__ dst, const float* __restrict__ bias,
           int M, int K, int epi,
           const float* __restrict__ bn_g, const float* __restrict__ bn_b,
           const float* __restrict__ bn_m, const float* __restrict__ bn_v,
           __half* __restrict__ out_h) {
    extern __shared__ __half sm[];
    const uint32_t sb = smem_u32(sm);
    const uint32_t stb = (SA_BUF + SB_BUF) * 2;

    const int tid  = threadIdx.x;
    const int lane = tid & 31;
    const int warp = tid >> 5;
    const int wm   = (warp & 1) * 64;
    const int wn   = (warp >> 1) * 64;
    const int row0 = blockIdx.y * BM;
    const int col0 = blockIdx.x * BN;
    const int NIT  = K / BK;

    const int g = lane >> 2;
    const int c = lane & 3;

    const uint32_t a_off = (((lane & 15) * AST) + ((lane >> 4) * 8)) * 2;
    const uint32_t b_off = ((((lane & 7) + ((lane >> 4) << 3)) * AST)
                            + (((lane >> 3) & 1) * 8)) * 2;

    float acc[4][8][4];
    #pragma unroll
    for (int i = 0; i < 4; i++)
        #pragma unroll
        for (int j = 0; j < 8; j++) {
            acc[i][j][0] = 0.f; acc[i][j][1] = 0.f;
            acc[i][j][2] = 0.f; acc[i][j][3] = 0.f;
        }

    auto load_buf = [&](int it) {
        const int st = it % STAGES;
        const int k0 = it * BK;
        const uint32_t sA = sb + st * stb;
        const uint32_t sB = sA + SA_BUF * 2;
        #pragma unroll
        for (int i = 0; i < 2; i++) {
            int q = tid + i * 256;
            int r = q >> 2, ch = q & 3;
            int grow = row0 + r;
            const __half* src = A + (long long)(grow < M ? grow : M - 1) * K + k0 + ch * 8;
            cp16(sA + (r * AST + ch * 8) * 2, src, (grow < M) ? 16 : 0);
        }
        #pragma unroll
        for (int i = 0; i < 4; i++) {
            int q = tid + i * 256;
            int r = q >> 2, ch = q & 3;
            const __half* src = W + (long long)(col0 + r) * K + k0 + ch * 8;
            cp16(sB + (r * AST + ch * 8) * 2, src, 16);
        }
        asm volatile("cp.async.commit_group;" ::: "memory");
    };

    load_buf(0);
    load_buf(1);

    for (int it = 0; it < NIT; it++) {
        if (it + 1 < NIT)
            asm volatile("cp.async.wait_group 1;" ::: "memory");
        else
            asm volatile("cp.async.wait_group 0;" ::: "memory");
        __syncthreads();
        if (it + 2 < NIT) load_buf(it + 2);

        const int st = it % STAGES;
        const uint32_t sA = sb + st * stb;
        const uint32_t sB = sA + SA_BUF * 2;

        #pragma unroll
        for (int ks = 0; ks < 2; ks++) {
            uint32_t af[4][4], bf[8][2];
            #pragma unroll
            for (int mt = 0; mt < 4; mt++)
                ldsm4(af[mt][0], af[mt][1], af[mt][2], af[mt][3],
                      sA + a_off + (uint32_t)((wm + mt * 16) * AST * 2) + ks * 32);
            #pragma unroll
            for (int p = 0; p < 4; p++)
                ldsm4(bf[2*p][0], bf[2*p][1], bf[2*p+1][0], bf[2*p+1][1],
                      sB + b_off + (uint32_t)((wn + p * 16) * AST * 2) + ks * 32);
            #pragma unroll
            for (int mt = 0; mt < 4; mt++)
                #pragma unroll
                for (int nt = 0; nt < 8; nt++)
                    mma16n8k16(acc[mt][nt], af[mt], bf[nt]);
        }
    }

    if (epi == 0) {
        #pragma unroll
        for (int mt = 0; mt < 4; mt++) {
            int r0 = row0 + wm + mt * 16 + g;
            #pragma unroll
            for (int nt = 0; nt < 8; nt++) {
                int cc = col0 + wn + nt * 8 + c * 2;
                float2 b = *(const float2*)&bias[cc];
                if (r0 < M)
                    *(float2*)&dst[(long long)r0 * 768 + cc] =
                        make_float2(acc[mt][nt][0] + b.x, acc[mt][nt][1] + b.y);
                if (r0 + 8 < M)
                    *(float2*)&dst[(long long)(r0 + 8) * 768 + cc] =
                        make_float2(acc[mt][nt][2] + b.x, acc[mt][nt][3] + b.y);
            }
        }
    } else {
        // fused bias + BN(eval) + ReLU, half output to layer-2 A operand
        #pragma unroll
        for (int mt = 0; mt < 4; mt++) {
            int r0 = row0 + wm + mt * 16 + g;
            #pragma unroll
            for (int nt = 0; nt < 8; nt++) {
                int cc = col0 + wn + nt * 8 + c * 2;
                float2 b  = *(const float2*)&bias[cc];
                float2 gm = *(const float2*)&bn_g[cc];
                float2 bt = *(const float2*)&bn_b[cc];
                float2 mn = *(const float2*)&bn_m[cc];
                float2 vr = *(const float2*)&bn_v[cc];
                float s0 = rsqrtf(vr.x + 1e-5f) * gm.x;
                float s1 = rsqrtf(vr.y + 1e-5f) * gm.y;
                float lo0 = fmaxf((acc[mt][nt][0] + b.x - mn.x) * s0 + bt.x, 0.f);
                float lo1 = fmaxf((acc[mt][nt][1] + b.y - mn.y) * s1 + bt.y, 0.f);
                float hi0 = fmaxf((acc[mt][nt][2] + b.x - mn.x) * s0 + bt.x, 0.f);
                float hi1 = fmaxf((acc[mt][nt][3] + b.y - mn.y) * s1 + bt.y, 0.f);
                if (r0 < M)
                    *(__half2*)&out_h[(size_t)r0 * K2 + cc] = __floats2half2_rn(lo0, lo1);
                if (r0 + 8 < M)
                    *(__half2*)&out_h[(size_t)(r0 + 8) * K2 + cc] = __floats2half2_rn(hi0, hi1);
            }
        }
    }
}

// ---------------- index-width detection (int32 vs int64 dump) ----------------
__global__ void k_detect(const int* ei) {
    __shared__ int found;
    if (threadIdx.x == 0) found = 0;
    __syncthreads();
    for (int i = threadIdx.x; i < 2048; i += blockDim.x)
        if (ei[2 * i + 1] != 0) found = 1;
    __syncthreads();
    if (threadIdx.x == 0) g_is64 = (found == 0) ? 1 : 0;
}
__device__ __forceinline__ int idx_at(const void* p, long long i, int is64) {
    return is64 ? (int)((const long long*)p)[i] : ((const int*)p)[i];
}

// ---------------- edge preprocessing / CSR build (scan-free) ----------------
__global__ void k_zero() {
    int i = blockIdx.x * blockDim.x + threadIdx.x;
    if (i < N_NODES * N_REL) g_cnt[i] = 0;
    if (i < N_NODES) g_deg[i] = 0;
    if (i == 0) g_total = 0;
}
__global__ void k_prep(const void* ei, const void* et) {
    int e = blockIdx.x * blockDim.x + threadIdx.x;
    if (e >= N_EDGES) return;
    int is64 = g_is64;
    int s = idx_at(ei, e, is64);
    int d = idx_at(ei, (long long)N_EDGES + e, is64);
    int t = idx_at(et, e, is64);
    g_esrc[e] = s; g_edst[e] = d; g_etyp[e] = t;
    atomicAdd(&g_cnt[d * N_REL + t], 1);
    atomicAdd(&g_deg[d], 1);
}
__global__ void k_alloc() {
    int i = blockIdx.x * blockDim.x + threadIdx.x;
    if (i >= N_NODES) return;
    g_off[i] = atomicAdd(&g_total, g_deg[i]);
    g_pos[i] = 0;
}
__global__ void k_fill() {
    int e = blockIdx.x * blockDim.x + threadIdx.x;
    if (e >= N_EDGES) return;
    int d = g_edst[e];
    int t = g_etyp[e];
    int p = atomicAdd(&g_pos[d], 1);
    float scl = 1.0f / (float)g_cnt[d * N_REL + t];
    g_es[g_off[d] + p] = make_int2(g_esrc[e] | (t << 20), __float_as_int(scl));
}

// ---------------- A conversion: x float -> g_A1[:, 0:256] half ---------------
__global__ void k_cvtA1(const float* __restrict__ x) {
    long long i = (long long)blockIdx.x * blockDim.x + threadIdx.x;  // half2 units
    if (i >= (long long)N_NODES * 128) return;
    int n  = (int)(i >> 7);
    int c2 = (int)(i & 127);
    float2 v = ((const float2*)x)[(long long)n * 128 + c2];
    *(__half2*)&g_A1[(size_t)n * K1 + c2 * 2] = __floats2half2_rn(v.x, v.y);
}

// ---------------- basis-combined CSR aggregation (unroll-2, MLP=2) -----------
// One block per dst node, Fin/4 threads. Z_b[n] = sum_edges comp[t,b]/cnt * A[src]
__global__ void k_aggZ(__half* __restrict__ Abase, const float* __restrict__ comp,
                       int Fin, int K) {
    __shared__ float scomp[N_REL * N_BASES];
    int n = blockIdx.x;
    int tid = threadIdx.x;
    if (tid < N_REL * N_BASES) scomp[tid] = comp[tid];
    __syncthreads();
    int beg = g_off[n], deg = g_deg[n];
    float z0[4] = {}, z1[4] = {}, z2[4] = {}, z3[4] = {};
    int j = 0;
    for (; j + 2 <= deg; j += 2) {
        int2 m0 = g_es[beg + j];
        int2 m1 = g_es[beg + j + 1];
        int sA = m0.x & 0xFFFFF, tA = m0.x >> 20;
        int sB = m1.x & 0xFFFFF, tB = m1.x >> 20;
        const __half2* hA = (const __half2*)&Abase[(size_t)sA * K + tid * 4];
        const __half2* hB = (const __half2*)&Abase[(size_t)sB * K + tid * 4];
        float2 a0 = __half22float2(hA[0]);
        float2 a1 = __half22float2(hA[1]);
        float2 b0 = __half22float2(hB[0]);
        float2 b1 = __half22float2(hB[1]);
        float fA = __int_as_float(m0.y), fB = __int_as_float(m1.y);
        float cA0 = scomp[tA*4+0]*fA, cA1 = scomp[tA*4+1]*fA;
        float cA2 = scomp[tA*4+2]*fA, cA3 = scomp[tA*4+3]*fA;
        float cB0 = scomp[tB*4+0]*fB, cB1 = scomp[tB*4+1]*fB;
        float cB2 = scomp[tB*4+2]*fB, cB3 = scomp[tB*4+3]*fB;
        float vA[4] = { a0.x, a0.y, a1.x, a1.y };
        float vB[4] = { b0.x, b0.y, b1.x, b1.y };
        #pragma unroll
        for (int i = 0; i < 4; i++) {
            z0[i] = fmaf(vA[i], cA0, fmaf(vB[i], cB0, z0[i]));
            z1[i] = fmaf(vA[i], cA1, fmaf(vB[i], cB1, z1[i]));
            z2[i] = fmaf(vA[i], cA2, fmaf(vB[i], cB2, z2[i]));
            z3[i] = fmaf(vA[i], cA3, fmaf(vB[i], cB3, z3[i]));
        }
    }
    if (j < deg) {
        int2 m0 = g_es[beg + j];
        int sA = m0.x & 0xFFFFF, tA = m0.x >> 20;
        const __half2* hA = (const __half2*)&Abase[(size_t)sA * K + tid * 4];
        float2 a0 = __half22float2(hA[0]);
        float2 a1 = __half22float2(hA[1]);
        float fA = __int_as_float(m0.y);
        float cA0 = scomp[tA*4+0]*fA, cA1 = scomp[tA*4+1]*fA;
        float cA2 = scomp[tA*4+2]*fA, cA3 = scomp[tA*4+3]*fA;
        float vA[4] = { a0.x, a0.y, a1.x, a1.y };
        #pragma unroll
        for (int i = 0; i < 4; i++) {
            z0[i] = fmaf(vA[i], cA0, z0[i]);
            z1[i] = fmaf(vA[i], cA1, z1[i]);
            z2[i] = fmaf(vA[i], cA2, z2[i]);
            z3[i] = fmaf(vA[i], cA3, z3[i]);
        }
    }
    __half2* d0 = (__half2*)&Abase[(size_t)n * K + Fin * 1 + tid * 4];
    __half2* d1 = (__half2*)&Abase[(size_t)n * K + Fin * 2 + tid * 4];
    __half2* d2 = (__half2*)&Abase[(size_t)n * K + Fin * 3 + tid * 4];
    __half2* d3 = (__half2*)&Abase[(size_t)n * K + Fin * 4 + tid * 4];
    d0[0] = __floats2half2_rn(z0[0], z0[1]); d0[1] = __floats2half2_rn(z0[2], z0[3]);
    d1[0] = __floats2half2_rn(z1[0], z1[1]); d1[1] = __floats2half2_rn(z1[2], z1[3]);
    d2[0] = __floats2half2_rn(z2[0], z2[1]); d2[1] = __floats2half2_rn(z2[2], z2[3]);
    d3[0] = __floats2half2_rn(z3[0], z3[1]); d3[1] = __floats2half2_rn(z3[2], z3[3]);
}

// ---------------- weight build: W[j, kidx] (K-major), j<768 ------------------
__global__ void k_buildW(const float* __restrict__ root,
                         const float* __restrict__ basis, int Fin, int K,
                         __half* __restrict__ W) {
    long long i = (long long)blockIdx.x * blockDim.x + threadIdx.x;
    long long tot = (long long)768 * K;
    if (i >= tot) return;
    int j = (int)(i / K), kidx = (int)(i % K);
    float v;
    if (kidx < Fin) {
        v = root[(long long)kidx * 768 + j];
    } else {
        int t = kidx - Fin;
        int b = t / Fin, k = t % Fin;
        v = basis[((long long)b * Fin + k) * 768 + j];
    }
    W[i] = __float2half_rn(v);
}

// ---------------- L2 normalize ----------------
__global__ void k_l2norm(float* __restrict__ out) {
    int n = blockIdx.x;
    float4 v = *(float4*)&out[(long long)n * 768 + threadIdx.x * 4];
    float ss = v.x*v.x + v.y*v.y + v.z*v.z + v.w*v.w;
    #pragma unroll
    for (int o = 16; o > 0; o >>= 1)
        ss += __shfl_xor_sync(0xffffffffu, ss, o);
    __shared__ float sw[6];
    __shared__ float s_inv;
    int wid = threadIdx.x / 32;
    if ((threadIdx.x & 31) == 0) sw[wid] = ss;
    __syncthreads();
    if (threadIdx.x == 0) {
        float tot = sw[0] + sw[1] + sw[2] + sw[3] + sw[4] + sw[5];
        s_inv = 1.0f / fmaxf(sqrtf(tot), 1e-12f);
    }
    __syncthreads();
    float inv = s_inv;
    v.x *= inv; v.y *= inv; v.z *= inv; v.w *= inv;
    *(float4*)&out[(long long)n * 768 + threadIdx.x * 4] = v;
}

// ---------------- launch ----------------
extern "C" void kernel_launch(void* const* d_in, const int* in_sizes, int n_in,
                              void* d_out, int out_size) {
    const float* x       = (const float*)d_in[0];
    const void*  ei      = d_in[1];
    const void*  et      = d_in[2];
    const float* basis1  = (const float*)d_in[3];
    const float* comp1   = (const float*)d_in[4];
    const float* root1   = (const float*)d_in[5];
    const float* bias1   = (const float*)d_in[6];
    const float* bn_g    = (const float*)d_in[7];
    const float* bn_b    = (const float*)d_in[8];
    const float* bn_m    = (const float*)d_in[9];
    const float* bn_v    = (const float*)d_in[10];
    const float* basis2  = (const float*)d_in[11];
    const float* comp2   = (const float*)d_in[12];
    const float* root2   = (const float*)d_in[13];
    const float* bias2   = (const float*)d_in[14];
    float* out = (float*)d_out;

    __half* g_A1_p;  cudaGetSymbolAddress((void**)&g_A1_p,  g_A1);
    __half* g_A2_p;  cudaGetSymbolAddress((void**)&g_A2_p,  g_A2);
    __half* g_W1_p;  cudaGetSymbolAddress((void**)&g_W1_p,  g_Wh1);
    __half* g_W2_p;  cudaGetSymbolAddress((void**)&g_W2_p,  g_Wh2);

    cudaFuncSetAttribute(k_gemm_mma, cudaFuncAttributeMaxDynamicSharedMemorySize, SM_TOTAL);

    const int EB = (N_EDGES + 255) / 256;
    dim3 gemm_grid(768 / BN, (N_NODES + BM - 1) / BM);

    cudaStream_t s1;
    cudaEvent_t evF, evC, evW1, evW2;
    cudaStreamCreateWithFlags(&s1, cudaStreamNonBlocking);
    cudaEventCreateWithFlags(&evF,  cudaEventDisableTiming);
    cudaEventCreateWithFlags(&evC,  cudaEventDisableTiming);
    cudaEventCreateWithFlags(&evW1, cudaEventDisableTiming);
    cudaEventCreateWithFlags(&evW2, cudaEventDisableTiming);

    k_detect<<<1, 256>>>((const int*)ei);
    cudaEventRecord(evF, 0);
    cudaStreamWaitEvent(s1, evF, 0);

    // ---- branch s1: features first (unblocks aggZ1 asap), then weights ----
    k_cvtA1<<<(int)(((long long)N_NODES * 128 + 255) / 256), 256, 0, s1>>>(x);
    cudaEventRecord(evC, s1);
    k_buildW<<<(int)(((long long)768 * K1 + 255) / 256), 256, 0, s1>>>(root1, basis1, IN_CH, K1, g_W1_p);
    cudaEventRecord(evW1, s1);
    k_buildW<<<(int)(((long long)768 * K2 + 255) / 256), 256, 0, s1>>>(root2, basis2, HID, K2, g_W2_p);
    cudaEventRecord(evW2, s1);

    // ---- branch 0: edge preprocessing + CSR build ----
    k_zero<<<(N_NODES * N_REL + 255) / 256, 256>>>();
    k_prep<<<EB, 256>>>(ei, et);
    k_alloc<<<(N_NODES + 255) / 256, 256>>>();
    k_fill<<<EB, 256>>>();

    // aggZ1 needs only cvtA1 + fill (buildW kernels may still be running)
    cudaStreamWaitEvent(0, evC, 0);
    k_aggZ<<<N_NODES, IN_CH / 4>>>(g_A1_p, comp1, IN_CH, K1);

    // ---- layer 1 GEMM (needs buildW1; epilogue: bias + BN + ReLU -> g_A2) ----
    cudaStreamWaitEvent(0, evW1, 0);
    k_gemm_mma<<<gemm_grid, 256, SM_TOTAL>>>(g_A1_p, g_W1_p, nullptr, bias1, N_NODES, K1, 1,
                                             bn_g, bn_b, bn_m, bn_v, g_A2_p);

    // ---- layer 2 ----
    k_aggZ<<<N_NODES, HID / 4>>>(g_A2_p, comp2, HID, K2);
    cudaStreamWaitEvent(0, evW2, 0);
    k_gemm_mma<<<gemm_grid, 256, SM_TOTAL>>>(g_A2_p, g_W2_p, out, bias2, N_NODES, K2, 0,
                                             nullptr, nullptr, nullptr, nullptr, nullptr);
    k_l2norm<<<N_NODES, 192>>>(out);

    cudaStreamDestroy(s1);
    cudaEventDestroy(evF);
    cudaEventDestroy(evC);
    cudaEventDestroy(evW1);
    cudaEventDestroy(evW2);
}

// round 13
// speedup vs baseline: 1.1200x; 1.0130x over previous
#include <cuda_runtime.h>
#include <cuda_fp16.h>
#include <cstdint>
#include <math.h>

#define N_NODES 50000
#define N_EDGES 200000
#define IN_CH   256
#define HID     768
#define N_REL   5
#define N_BASES 4
#define K1      (5*IN_CH)   /* 1280: [x | Z0..Z3] layer 1 */
#define K2      (5*HID)     /* 3840: [h | Z0..Z3] layer 2 */

// ---------------- static device scratch (no allocations allowed) -------------
__device__ __half g_A1[(size_t)N_NODES * K1];   // layer-1 GEMM A operand (122 MB)
__device__ __half g_A2[(size_t)N_NODES * K2];   // layer-2 GEMM A operand (366 MB)
__device__ __half g_Wh1[(size_t)HID * K1];      // layer-1 B^T (K-major, half)
__device__ __half g_Wh2[(size_t)HID * K2];      // layer-2 B^T (K-major, half)
__device__ int    g_cnt[N_NODES * N_REL];
__device__ int    g_deg[N_NODES];
__device__ int    g_off[N_NODES];
__device__ int    g_pos[N_NODES];
__device__ int2   g_es[N_EDGES];                // per-slot {src|(t<<20), bits(1/cnt)}
__device__ int    g_esrc[N_EDGES];
__device__ int    g_edst[N_EDGES];
__device__ int    g_etyp[N_EDGES];
__device__ int    g_total;
__device__ int    g_is64;

// ============================ helpers ====================================
__device__ __forceinline__ void cp16(uint32_t dst, const void* src, int sz) {
    asm volatile("cp.async.cg.shared.global [%0], [%1], 16, %2;"
                 :: "r"(dst), "l"(src), "r"(sz));
}
__device__ __forceinline__ uint32_t smem_u32(const void* p) {
    uint32_t a;
    asm("{ .reg .u64 t; cvta.to.shared.u64 t, %1; cvt.u32.u64 %0, t; }"
        : "=r"(a) : "l"(p));
    return a;
}
__device__ __forceinline__ void mma16n8k16(float* d, const uint32_t* a, const uint32_t* b) {
    asm volatile(
        "mma.sync.aligned.m16n8k16.row.col.f32.f16.f16.f32 "
        "{%0,%1,%2,%3}, {%4,%5,%6,%7}, {%8,%9}, {%0,%1,%2,%3};"
        : "+f"(d[0]), "+f"(d[1]), "+f"(d[2]), "+f"(d[3])
        : "r"(a[0]), "r"(a[1]), "r"(a[2]), "r"(a[3]), "r"(b[0]), "r"(b[1]));
}
__device__ __forceinline__ void ldsm4(uint32_t& r0, uint32_t& r1, uint32_t& r2,
                                      uint32_t& r3, uint32_t addr) {
    asm volatile("ldmatrix.sync.aligned.m8n8.x4.shared.b16 {%0,%1,%2,%3}, [%4];"
                 : "=r"(r0), "=r"(r1), "=r"(r2), "=r"(r3) : "r"(addr));
}

// ====================== fp16 mma.sync GEMM (fp32 accum) ======================
// out = A[M, K] @ W^T + bias   (W is [768, K] K-major, half)
// epi=0: float out to dst[M,768].  epi=1: BN(eval)+ReLU, half out to
//        out_h[row*K2 + col] (layer-2 A operand feature block).
// rowBlkOff: row-block offset (grid.y covers a row-range slice).
#define BM 128
#define BN 256
#define BK 32
#define AST 40                              /* padded row stride in halves */
#define SA_BUF (BM * AST)
#define SB_BUF (BN * AST)
#define STAGES 3
#define SM_TOTAL (STAGES * (SA_BUF + SB_BUF) * 2)   /* 92160 bytes */

__global__ void __launch_bounds__(256, 1)
k_gemm_mma(const __half* __restrict__ A, const __half* __restrict__ W,
           float* __restrict__ dst, const float* __restrict__ bias,
           int M, int K, int epi, int rowBlkOff,
           const float* __restrict__ bn_g, const float* __restrict__ bn_b,
           const float* __restrict__ bn_m, const float* __restrict__ bn_v,
           __half* __restrict__ out_h) {
    extern __shared__ __half sm[];
    const uint32_t sb = smem_u32(sm);
    const uint32_t stb = (SA_BUF + SB_BUF) * 2;

    const int tid  = threadIdx.x;
    const int lane = tid & 31;
    const int warp = tid >> 5;
    const int wm   = (warp & 1) * 64;
    const int wn   = (warp >> 1) * 64;
    const int row0 = (blockIdx.y + rowBlkOff) * BM;
    const int col0 = blockIdx.x * BN;
    const int NIT  = K / BK;

    const int g = lane >> 2;
    const int c = lane & 3;

    const uint32_t a_off = (((lane & 15) * AST) + ((lane >> 4) * 8)) * 2;
    const uint32_t b_off = ((((lane & 7) + ((lane >> 4) << 3)) * AST)
                            + (((lane >> 3) & 1) * 8)) * 2;

    float acc[4][8][4];
    #pragma unroll
    for (int i = 0; i < 4; i++)
        #pragma unroll
        for (int j = 0; j < 8; j++) {
            acc[i][j][0] = 0.f; acc[i][j][1] = 0.f;
            acc[i][j][2] = 0.f; acc[i][j][3] = 0.f;
        }

    auto load_buf = [&](int it) {
        const int st = it % STAGES;
        const int k0 = it * BK;
        const uint32_t sA = sb + st * stb;
        const uint32_t sB = sA + SA_BUF * 2;
        #pragma unroll
        for (int i = 0; i < 2; i++) {
            int q = tid + i * 256;
            int r = q >> 2, ch = q & 3;
            int grow = row0 + r;
            const __half* src = A + (long long)(grow < M ? grow : M - 1) * K + k0 + ch * 8;
            cp16(sA + (r * AST + ch * 8) * 2, src, (grow < M) ? 16 : 0);
        }
        #pragma unroll
        for (int i = 0; i < 4; i++) {
            int q = tid + i * 256;
            int r = q >> 2, ch = q & 3;
            const __half* src = W + (long long)(col0 + r) * K + k0 + ch * 8;
            cp16(sB + (r * AST + ch * 8) * 2, src, 16);
        }
        asm volatile("cp.async.commit_group;" ::: "memory");
    };

    load_buf(0);
    load_buf(1);

    for (int it = 0; it < NIT; it++) {
        if (it + 1 < NIT)
            asm volatile("cp.async.wait_group 1;" ::: "memory");
        else
            asm volatile("cp.async.wait_group 0;" ::: "memory");
        __syncthreads();
        if (it + 2 < NIT) load_buf(it + 2);

        const int st = it % STAGES;
        const uint32_t sA = sb + st * stb;
        const uint32_t sB = sA + SA_BUF * 2;

        #pragma unroll
        for (int ks = 0; ks < 2; ks++) {
            uint32_t af[4][4], bf[8][2];
            #pragma unroll
            for (int mt = 0; mt < 4; mt++)
                ldsm4(af[mt][0], af[mt][1], af[mt][2], af[mt][3],
                      sA + a_off + (uint32_t)((wm + mt * 16) * AST * 2) + ks * 32);
            #pragma unroll
            for (int p = 0; p < 4; p++)
                ldsm4(bf[2*p][0], bf[2*p][1], bf[2*p+1][0], bf[2*p+1][1],
                      sB + b_off + (uint32_t)((wn + p * 16) * AST * 2) + ks * 32);
            #pragma unroll
            for (int mt = 0; mt < 4; mt++)
                #pragma unroll
                for (int nt = 0; nt < 8; nt++)
                    mma16n8k16(acc[mt][nt], af[mt], bf[nt]);
        }
    }

    if (epi == 0) {
        #pragma unroll
        for (int mt = 0; mt < 4; mt++) {
            int r0 = row0 + wm + mt * 16 + g;
            #pragma unroll
            for (int nt = 0; nt < 8; nt++) {
                int cc = col0 + wn + nt * 8 + c * 2;
                float2 b = *(const float2*)&bias[cc];
                if (r0 < M)
                    *(float2*)&dst[(long long)r0 * 768 + cc] =
                        make_float2(acc[mt][nt][0] + b.x, acc[mt][nt][1] + b.y);
                if (r0 + 8 < M)
                    *(float2*)&dst[(long long)(r0 + 8) * 768 + cc] =
                        make_float2(acc[mt][nt][2] + b.x, acc[mt][nt][3] + b.y);
            }
        }
    } else {
        // fused bias + BN(eval) + ReLU, half output to layer-2 A operand
        #pragma unroll
        for (int mt = 0; mt < 4; mt++) {
            int r0 = row0 + wm + mt * 16 + g;
            #pragma unroll
            for (int nt = 0; nt < 8; nt++) {
                int cc = col0 + wn + nt * 8 + c * 2;
                float2 b  = *(const float2*)&bias[cc];
                float2 gm = *(const float2*)&bn_g[cc];
                float2 bt = *(const float2*)&bn_b[cc];
                float2 mn = *(const float2*)&bn_m[cc];
                float2 vr = *(const float2*)&bn_v[cc];
                float s0 = rsqrtf(vr.x + 1e-5f) * gm.x;
                float s1 = rsqrtf(vr.y + 1e-5f) * gm.y;
                float lo0 = fmaxf((acc[mt][nt][0] + b.x - mn.x) * s0 + bt.x, 0.f);
                float lo1 = fmaxf((acc[mt][nt][1] + b.y - mn.y) * s1 + bt.y, 0.f);
                float hi0 = fmaxf((acc[mt][nt][2] + b.x - mn.x) * s0 + bt.x, 0.f);
                float hi1 = fmaxf((acc[mt][nt][3] + b.y - mn.y) * s1 + bt.y, 0.f);
                if (r0 < M)
                    *(__half2*)&out_h[(size_t)r0 * K2 + cc] = __floats2half2_rn(lo0, lo1);
                if (r0 + 8 < M)
                    *(__half2*)&out_h[(size_t)(r0 + 8) * K2 + cc] = __floats2half2_rn(hi0, hi1);
            }
        }
    }
}

// ---------------- index-width detection (int32 vs int64 dump) ----------------
__global__ void k_detect(const int* ei) {
    __shared__ int found;
    if (threadIdx.x == 0) found = 0;
    __syncthreads();
    for (int i = threadIdx.x; i < 2048; i += blockDim.x)
        if (ei[2 * i + 1] != 0) found = 1;
    __syncthreads();
    if (threadIdx.x == 0) g_is64 = (found == 0) ? 1 : 0;
}
__device__ __forceinline__ int idx_at(const void* p, long long i, int is64) {
    return is64 ? (int)((const long long*)p)[i] : ((const int*)p)[i];
}

// ---------------- edge preprocessing / CSR build (scan-free) ----------------
__global__ void k_zero() {
    int i = blockIdx.x * blockDim.x + threadIdx.x;
    if (i < N_NODES * N_REL) g_cnt[i] = 0;
    if (i < N_NODES) g_deg[i] = 0;
    if (i == 0) g_total = 0;
}
__global__ void k_prep(const void* ei, const void* et) {
    int e = blockIdx.x * blockDim.x + threadIdx.x;
    if (e >= N_EDGES) return;
    int is64 = g_is64;
    int s = idx_at(ei, e, is64);
    int d = idx_at(ei, (long long)N_EDGES + e, is64);
    int t = idx_at(et, e, is64);
    g_esrc[e] = s; g_edst[e] = d; g_etyp[e] = t;
    atomicAdd(&g_cnt[d * N_REL + t], 1);
    atomicAdd(&g_deg[d], 1);
}
__global__ void k_alloc() {
    int i = blockIdx.x * blockDim.x + threadIdx.x;
    if (i >= N_NODES) return;
    g_off[i] = atomicAdd(&g_total, g_deg[i]);
    g_pos[i] = 0;
}
__global__ void k_fill() {
    int e = blockIdx.x * blockDim.x + threadIdx.x;
    if (e >= N_EDGES) return;
    int d = g_edst[e];
    int t = g_etyp[e];
    int p = atomicAdd(&g_pos[d], 1);
    float scl = 1.0f / (float)g_cnt[d * N_REL + t];
    g_es[g_off[d] + p] = make_int2(g_esrc[e] | (t << 20), __float_as_int(scl));
}

// ---------------- A conversion: x float -> g_A1[:, 0:256] half ---------------
__global__ void k_cvtA1(const float* __restrict__ x) {
    long long i = (long long)blockIdx.x * blockDim.x + threadIdx.x;  // half2 units
    if (i >= (long long)N_NODES * 128) return;
    int n  = (int)(i >> 7);
    int c2 = (int)(i & 127);
    float2 v = ((const float2*)x)[(long long)n * 128 + c2];
    *(__half2*)&g_A1[(size_t)n * K1 + c2 * 2] = __floats2half2_rn(v.x, v.y);
}

// ---------------- basis-combined CSR aggregation (unroll-2, MLP=2) -----------
// One block per dst node (blockIdx.x + nOff), Fin/4 threads.
__global__ void k_aggZ(__half* __restrict__ Abase, const float* __restrict__ comp,
                       int Fin, int K, int nOff) {
    __shared__ float scomp[N_REL * N_BASES];
    int n = blockIdx.x + nOff;
    int tid = threadIdx.x;
    if (tid < N_REL * N_BASES) scomp[tid] = comp[tid];
    __syncthreads();
    int beg = g_off[n], deg = g_deg[n];
    float z0[4] = {}, z1[4] = {}, z2[4] = {}, z3[4] = {};
    int j = 0;
    for (; j + 2 <= deg; j += 2) {
        int2 m0 = g_es[beg + j];
        int2 m1 = g_es[beg + j + 1];
        int sA = m0.x & 0xFFFFF, tA = m0.x >> 20;
        int sB = m1.x & 0xFFFFF, tB = m1.x >> 20;
        const __half2* hA = (const __half2*)&Abase[(size_t)sA * K + tid * 4];
        const __half2* hB = (const __half2*)&Abase[(size_t)sB * K + tid * 4];
        float2 a0 = __half22float2(hA[0]);
        float2 a1 = __half22float2(hA[1]);
        float2 b0 = __half22float2(hB[0]);
        float2 b1 = __half22float2(hB[1]);
        float fA = __int_as_float(m0.y), fB = __int_as_float(m1.y);
        float cA0 = scomp[tA*4+0]*fA, cA1 = scomp[tA*4+1]*fA;
        float cA2 = scomp[tA*4+2]*fA, cA3 = scomp[tA*4+3]*fA;
        float cB0 = scomp[tB*4+0]*fB, cB1 = scomp[tB*4+1]*fB;
        float cB2 = scomp[tB*4+2]*fB, cB3 = scomp[tB*4+3]*fB;
        float vA[4] = { a0.x, a0.y, a1.x, a1.y };
        float vB[4] = { b0.x, b0.y, b1.x, b1.y };
        #pragma unroll
        for (int i = 0; i < 4; i++) {
            z0[i] = fmaf(vA[i], cA0, fmaf(vB[i], cB0, z0[i]));
            z1[i] = fmaf(vA[i], cA1, fmaf(vB[i], cB1, z1[i]));
            z2[i] = fmaf(vA[i], cA2, fmaf(vB[i], cB2, z2[i]));
            z3[i] = fmaf(vA[i], cA3, fmaf(vB[i], cB3, z3[i]));
        }
    }
    if (j < deg) {
        int2 m0 = g_es[beg + j];
        int sA = m0.x & 0xFFFFF, tA = m0.x >> 20;
        const __half2* hA = (const __half2*)&Abase[(size_t)sA * K + tid * 4];
        float2 a0 = __half22float2(hA[0]);
        float2 a1 = __half22float2(hA[1]);
        float fA = __int_as_float(m0.y);
        float cA0 = scomp[tA*4+0]*fA, cA1 = scomp[tA*4+1]*fA;
        float cA2 = scomp[tA*4+2]*fA, cA3 = scomp[tA*4+3]*fA;
        float vA[4] = { a0.x, a0.y, a1.x, a1.y };
        #pragma unroll
        for (int i = 0; i < 4; i++) {
            z0[i] = fmaf(vA[i], cA0, z0[i]);
            z1[i] = fmaf(vA[i], cA1, z1[i]);
            z2[i] = fmaf(vA[i], cA2, z2[i]);
            z3[i] = fmaf(vA[i], cA3, z3[i]);
        }
    }
    __half2* d0 = (__half2*)&Abase[(size_t)n * K + Fin * 1 + tid * 4];
    __half2* d1 = (__half2*)&Abase[(size_t)n * K + Fin * 2 + tid * 4];
    __half2* d2 = (__half2*)&Abase[(size_t)n * K + Fin * 3 + tid * 4];
    __half2* d3 = (__half2*)&Abase[(size_t)n * K + Fin * 4 + tid * 4];
    d0[0] = __floats2half2_rn(z0[0], z0[1]); d0[1] = __floats2half2_rn(z0[2], z0[3]);
    d1[0] = __floats2half2_rn(z1[0], z1[1]); d1[1] = __floats2half2_rn(z1[2], z1[3]);
    d2[0] = __floats2half2_rn(z2[0], z2[1]); d2[1] = __floats2half2_rn(z2[2], z2[3]);
    d3[0] = __floats2half2_rn(z3[0], z3[1]); d3[1] = __floats2half2_rn(z3[2], z3[3]);
}

// ---------------- weight build: W[j, kidx] (K-major), j<768 ------------------
__global__ void k_buildW(const float* __restrict__ root,
                         const float* __restrict__ basis, int Fin, int K,
                         __half* __restrict__ W) {
    long long i = (long long)blockIdx.x * blockDim.x + threadIdx.x;
    long long tot = (long long)768 * K;
    if (i >= tot) return;
    int j = (int)(i / K), kidx = (int)(i % K);
    float v;
    if (kidx < Fin) {
        v = root[(long long)kidx * 768 + j];
    } else {
        int t = kidx - Fin;
        int b = t / Fin, k = t % Fin;
        v = basis[((long long)b * Fin + k) * 768 + j];
    }
    W[i] = __float2half_rn(v);
}

// ---------------- L2 normalize (node offset for row-sliced launch) ----------
__global__ void k_l2norm(float* __restrict__ out, int nOff) {
    int n = blockIdx.x + nOff;
    float4 v = *(float4*)&out[(long long)n * 768 + threadIdx.x * 4];
    float ss = v.x*v.x + v.y*v.y + v.z*v.z + v.w*v.w;
    #pragma unroll
    for (int o = 16; o > 0; o >>= 1)
        ss += __shfl_xor_sync(0xffffffffu, ss, o);
    __shared__ float sw[6];
    __shared__ float s_inv;
    int wid = threadIdx.x / 32;
    if ((threadIdx.x & 31) == 0) sw[wid] = ss;
    __syncthreads();
    if (threadIdx.x == 0) {
        float tot = sw[0] + sw[1] + sw[2] + sw[3] + sw[4] + sw[5];
        s_inv = 1.0f / fmaxf(sqrtf(tot), 1e-12f);
    }
    __syncthreads();
    float inv = s_inv;
    v.x *= inv; v.y *= inv; v.z *= inv; v.w *= inv;
    *(float4*)&out[(long long)n * 768 + threadIdx.x * 4] = v;
}

// ---------------- launch ----------------
extern "C" void kernel_launch(void* const* d_in, const int* in_sizes, int n_in,
                              void* d_out, int out_size) {
    const float* x       = (const float*)d_in[0];
    const void*  ei      = d_in[1];
    const void*  et      = d_in[2];
    const float* basis1  = (const float*)d_in[3];
    const float* comp1   = (const float*)d_in[4];
    const float* root1   = (const float*)d_in[5];
    const float* bias1   = (const float*)d_in[6];
    const float* bn_g    = (const float*)d_in[7];
    const float* bn_b    = (const float*)d_in[8];
    const float* bn_m    = (const float*)d_in[9];
    const float* bn_v    = (const float*)d_in[10];
    const float* basis2  = (const float*)d_in[11];
    const float* comp2   = (const float*)d_in[12];
    const float* root2   = (const float*)d_in[13];
    const float* bias2   = (const float*)d_in[14];
    float* out = (float*)d_out;

    __half* g_A1_p;  cudaGetSymbolAddress((void**)&g_A1_p,  g_A1);
    __half* g_A2_p;  cudaGetSymbolAddress((void**)&g_A2_p,  g_A2);
    __half* g_W1_p;  cudaGetSymbolAddress((void**)&g_W1_p,  g_Wh1);
    __half* g_W2_p;  cudaGetSymbolAddress((void**)&g_W2_p,  g_Wh2);

    cudaFuncSetAttribute(k_gemm_mma, cudaFuncAttributeMaxDynamicSharedMemorySize, SM_TOTAL);

    const int EB = (N_EDGES + 255) / 256;
    const int RB_A = 196, RB_B = 195;          // row blocks: 196+195 = 391
    const int NA   = RB_A * BM;                // 25088 nodes in slice A
    const int NB   = N_NODES - NA;             // 24912 nodes in slice B
    dim3 gridA(768 / BN, RB_A), gridB(768 / BN, RB_B);

    cudaStream_t s1;
    cudaEvent_t evF, evC, evW1, evW2, evZ1A, evZ2A, evG1A, evG1B, evDone;
    cudaStreamCreateWithFlags(&s1, cudaStreamNonBlocking);
    cudaEventCreateWithFlags(&evF,    cudaEventDisableTiming);
    cudaEventCreateWithFlags(&evC,    cudaEventDisableTiming);
    cudaEventCreateWithFlags(&evW1,   cudaEventDisableTiming);
    cudaEventCreateWithFlags(&evW2,   cudaEventDisableTiming);
    cudaEventCreateWithFlags(&evZ1A,  cudaEventDisableTiming);
    cudaEventCreateWithFlags(&evZ2A,  cudaEventDisableTiming);
    cudaEventCreateWithFlags(&evG1A,  cudaEventDisableTiming);
    cudaEventCreateWithFlags(&evG1B,  cudaEventDisableTiming);
    cudaEventCreateWithFlags(&evDone, cudaEventDisableTiming);

    cudaEvent_t evFill;
    cudaEventCreateWithFlags(&evFill, cudaEventDisableTiming);

    k_detect<<<1, 256>>>((const int*)ei);
    cudaEventRecord(evF, 0);
    cudaStreamWaitEvent(s1, evF, 0);

    // ---- s1: features + layer-1 weights ----
    k_cvtA1<<<(int)(((long long)N_NODES * 128 + 255) / 256), 256, 0, s1>>>(x);
    cudaEventRecord(evC, s1);
    k_buildW<<<(int)(((long long)768 * K1 + 255) / 256), 256, 0, s1>>>(root1, basis1, IN_CH, K1, g_W1_p);
    cudaEventRecord(evW1, s1);

    // ---- s0: edge preprocessing + CSR build ----
    k_zero<<<(N_NODES * N_REL + 255) / 256, 256>>>();
    k_prep<<<EB, 256>>>(ei, et);
    k_alloc<<<(N_NODES + 255) / 256, 256>>>();
    k_fill<<<EB, 256>>>();
    cudaEventRecord(evFill, 0);

    // ---- layer 1: aggZ1-A -> GEMM1-A (s0) ; aggZ1-B -> GEMM1-B (s1) ----
    cudaStreamWaitEvent(0, evC, 0);
    k_aggZ<<<NA, IN_CH / 4>>>(g_A1_p, comp1, IN_CH, K1, 0);
    cudaEventRecord(evZ1A, 0);
    cudaStreamWaitEvent(0, evW1, 0);
    k_gemm_mma<<<gridA, 256, SM_TOTAL>>>(g_A1_p, g_W1_p, nullptr, bias1, N_NODES, K1, 1, 0,
                                         bn_g, bn_b, bn_m, bn_v, g_A2_p);
    cudaEventRecord(evG1A, 0);

    cudaStreamWaitEvent(s1, evFill, 0);
    cudaStreamWaitEvent(s1, evZ1A, 0);   // stagger: B-agg overlaps GEMM1-A
    k_aggZ<<<NB, IN_CH / 4, 0, s1>>>(g_A1_p, comp1, IN_CH, K1, NA);
    k_gemm_mma<<<gridB, 256, SM_TOTAL, s1>>>(g_A1_p, g_W1_p, nullptr, bias1, N_NODES, K1, 1, RB_A,
                                             bn_g, bn_b, bn_m, bn_v, g_A2_p);
    cudaEventRecord(evG1B, s1);
    k_buildW<<<(int)(((long long)768 * K2 + 255) / 256), 256, 0, s1>>>(root2, basis2, HID, K2, g_W2_p);
    cudaEventRecord(evW2, s1);

    // ---- layer 2: aggZ2-A -> GEMM2-A -> l2norm-A (s0) ;
    //               aggZ2-B (staggered) -> GEMM2-B -> l2norm-B (s1) ----
    cudaStreamWaitEvent(0, evG1B, 0);    // aggZ2 needs ALL of GEMM1 (random src rows)
    k_aggZ<<<NA, HID / 4>>>(g_A2_p, comp2, HID, K2, 0);
    cudaEventRecord(evZ2A, 0);
    cudaStreamWaitEvent(0, evW2, 0);
    k_gemm_mma<<<gridA, 256, SM_TOTAL>>>(g_A2_p, g_W2_p, out, bias2, N_NODES, K2, 0, 0,
                                         nullptr, nullptr, nullptr, nullptr, nullptr);
    k_l2norm<<<NA, 192>>>(out, 0);

    cudaStreamWaitEvent(s1, evG1A, 0);
    cudaStreamWaitEvent(s1, evZ2A, 0);   // stagger: B-agg overlaps GEMM2-A
    k_aggZ<<<NB, HID / 4, 0, s1>>>(g_A2_p, comp2, HID, K2, NA);
    k_gemm_mma<<<gridB, 256, SM_TOTAL, s1>>>(g_A2_p, g_W2_p, out, bias2, N_NODES, K2, 0, RB_A,
                                             nullptr, nullptr, nullptr, nullptr, nullptr);
    k_l2norm<<<NB, 192, 0, s1>>>(out, NA);
    cudaEventRecord(evDone, s1);

    // join all forked work back to the capture stream
    cudaStreamWaitEvent(0, evDone, 0);

    cudaStreamDestroy(s1);
    cudaEventDestroy(evF);
    cudaEventDestroy(evC);
    cudaEventDestroy(evW1);
    cudaEventDestroy(evW2);
    cudaEventDestroy(evZ1A);
    cudaEventDestroy(evZ2A);
    cudaEventDestroy(evG1A);
    cudaEventDestroy(evG1B);
    cudaEventDestroy(evFill);
    cudaEventDestroy(evDone);
}